// round 14
// baseline (speedup 1.0000x reference)
#include <cuda_runtime.h>
#include <cstdint>

// CorrelationHead fused. Vectorized high-MLP LDG.128->STS.128 staging (raw layout),
// single __syncthreads, register-prefetched W, fmaf compute.
// out[b,o] = bias[o] + sum over 625 in-bounds (i,j,u,v):
//   W[o, p*1029+q*49+i*7+j] * dot_c( P1[b,c,i,j], P2[b,c,u,v] ),
//   u = i+2(p-10), v = j+2(q-10) in [0,6]; u≡i (mod 2), v≡j (mod 2).
//
// tid = slot*4 + cs. slot = r*4 + ijq, r = (v&1)*7 + u (14 rows). c = cs + 4*cl.
// Per iter: 8 LDS.32 -> 16 FMAs (4 ij x 4 v).

static constexpr int FEAT = 21609;          // 21*21*49
static constexpr int TEN  = 6272;           // 128*49 floats per tensor per batch
static constexpr int TEN4 = TEN / 4;        // 1568 float4 per tensor
static constexpr int S2_OFF   = TEN;
static constexpr int WRED_OFF = 2 * TEN + 16;     // 16-float zero pad absorbs OOB y tap
static constexpr int SMEM_BYTES = (WRED_OFF + 32) * 4;

__global__ __launch_bounds__(224, 4)
void corr_head_kernel(const float* __restrict__ p1,
                      const float* __restrict__ p2,
                      const float* __restrict__ W,
                      const float* __restrict__ bias,
                      float* __restrict__ out)
{
    extern __shared__ float sm[];
    float* s1   = sm;             // P1 raw: [c*49 + uv]
    float* s2   = sm + S2_OFF;    // P2 raw: [c*49 + uv]
    float* wred = sm + WRED_OFF;  // 7 warps * 4 outputs

    const int b   = blockIdx.x;
    const int tid = threadIdx.x;

    // ---- Per-thread geometry ----
    const int cs   = tid & 3;
    const int slot = tid >> 2;          // 0..55
    const int r    = slot >> 2;         // 0..13
    const int ijq  = slot & 3;
    const int jpar = (r >= 7) ? 1 : 0;
    const int u    = r - jpar * 7;
    const int ipar = u & 1;
    const int ni   = 4 - ipar;
    const int nj   = 4 - jpar;
    const int nvi  = 4 - jpar;

    int xb[4];
    #pragma unroll
    for (int t = 0; t < 4; t++) {
        int idx = ijq * 4 + t;
        int a_  = (nj == 4) ? (idx >> 2) : (idx / 3);
        int b_  = idx - a_ * nj;
        int ij  = (ipar + 2 * a_) * 7 + (jpar + 2 * b_);
        xb[t]   = ((idx < ni * nj) ? ij : 0) + cs * 49;
    }
    const int yb = u * 7 + jpar + cs * 49;

    // ---- W prefetch into registers (independent LDGs, overlap with staging) ----
    float wv[16];
    {
        const float* Wo = W + cs * FEAT;
        #pragma unroll
        for (int t = 0; t < 4; t++) {
            int idx = ijq * 4 + t;
            bool val = idx < ni * nj;
            int a_  = (nj == 4) ? (idx >> 2) : (idx / 3);
            int b_  = idx - a_ * nj;
            int ij  = (ipar + 2 * a_) * 7 + (jpar + 2 * b_);
            int wb  = (10 + (u >> 1) - a_) * 1029 + (10 - b_) * 49 + ij;
            wv[t*4+0] = val ? __ldg(Wo + wb)       : 0.f;
            wv[t*4+1] = val ? __ldg(Wo + wb + 49)  : 0.f;
            wv[t*4+2] = val ? __ldg(Wo + wb + 98)  : 0.f;
            wv[t*4+3] = (val && nvi == 4) ? __ldg(Wo + wb + 147) : 0.f;
        }
    }

    // ---- Staging: raw contiguous copy, 14 independent LDG.128 -> STS.128 ----
    {
        const float4* g1 = reinterpret_cast<const float4*>(p1 + (size_t)b * TEN);
        const float4* g2 = reinterpret_cast<const float4*>(p2 + (size_t)b * TEN);
        float4* d1 = reinterpret_cast<float4*>(s1);
        float4* d2 = reinterpret_cast<float4*>(s2);
        float4 t1[7], t2[7];
        #pragma unroll
        for (int m = 0; m < 7; m++) t1[m] = __ldg(g1 + tid + m * 224);
        #pragma unroll
        for (int m = 0; m < 7; m++) t2[m] = __ldg(g2 + tid + m * 224);
        #pragma unroll
        for (int m = 0; m < 7; m++) d1[tid + m * 224] = t1[m];
        #pragma unroll
        for (int m = 0; m < 7; m++) d2[tid + m * 224] = t2[m];
    }
    // Zero the 16-float OOB pad (the discarded jpar=1 vi=3 tap lands here; wv=0
    // kills its value but it must not be NaN-producing garbage).
    if (tid < 16) sm[2 * TEN + tid] = 0.f;
    __syncthreads();

    // ---- Compute: 32 c-steps, 8 LDS.32 + 16 fmaf per step ----
    float4 dot0 = {0,0,0,0}, dot1 = {0,0,0,0}, dot2 = {0,0,0,0}, dot3 = {0,0,0,0};
    #pragma unroll
    for (int cl = 0; cl < 32; cl++) {
        const int off = cl * 196;
        float y0 = s2[yb + off];
        float y1 = s2[yb + off + 2];
        float y2 = s2[yb + off + 4];
        float y3 = s2[yb + off + 6];
        float x0 = s1[xb[0] + off];
        float x1 = s1[xb[1] + off];
        float x2 = s1[xb[2] + off];
        float x3 = s1[xb[3] + off];
        dot0.x = fmaf(x0, y0, dot0.x); dot0.y = fmaf(x0, y1, dot0.y);
        dot0.z = fmaf(x0, y2, dot0.z); dot0.w = fmaf(x0, y3, dot0.w);
        dot1.x = fmaf(x1, y0, dot1.x); dot1.y = fmaf(x1, y1, dot1.y);
        dot1.z = fmaf(x1, y2, dot1.z); dot1.w = fmaf(x1, y3, dot1.w);
        dot2.x = fmaf(x2, y0, dot2.x); dot2.y = fmaf(x2, y1, dot2.y);
        dot2.z = fmaf(x2, y2, dot2.z); dot2.w = fmaf(x2, y3, dot2.w);
        dot3.x = fmaf(x3, y0, dot3.x); dot3.y = fmaf(x3, y1, dot3.y);
        dot3.z = fmaf(x3, y2, dot3.z); dot3.w = fmaf(x3, y3, dot3.w);
    }

    // ---- Reduce partial dots across the 4 cs lanes ----
    const unsigned FULL = 0xffffffffu;
    #pragma unroll
    for (int off = 1; off < 4; off <<= 1) {
        dot0.x += __shfl_xor_sync(FULL, dot0.x, off);
        dot0.y += __shfl_xor_sync(FULL, dot0.y, off);
        dot0.z += __shfl_xor_sync(FULL, dot0.z, off);
        dot0.w += __shfl_xor_sync(FULL, dot0.w, off);
        dot1.x += __shfl_xor_sync(FULL, dot1.x, off);
        dot1.y += __shfl_xor_sync(FULL, dot1.y, off);
        dot1.z += __shfl_xor_sync(FULL, dot1.z, off);
        dot1.w += __shfl_xor_sync(FULL, dot1.w, off);
        dot2.x += __shfl_xor_sync(FULL, dot2.x, off);
        dot2.y += __shfl_xor_sync(FULL, dot2.y, off);
        dot2.z += __shfl_xor_sync(FULL, dot2.z, off);
        dot2.w += __shfl_xor_sync(FULL, dot2.w, off);
        dot3.x += __shfl_xor_sync(FULL, dot3.x, off);
        dot3.y += __shfl_xor_sync(FULL, dot3.y, off);
        dot3.z += __shfl_xor_sync(FULL, dot3.z, off);
        dot3.w += __shfl_xor_sync(FULL, dot3.w, off);
    }

    // ---- Epilogue: branchless W combine (invalid/unused taps have wv = 0) ----
    float part = 0.f;
    part = fmaf(dot0.x, wv[0],  part); part = fmaf(dot0.y, wv[1],  part);
    part = fmaf(dot0.z, wv[2],  part); part = fmaf(dot0.w, wv[3],  part);
    part = fmaf(dot1.x, wv[4],  part); part = fmaf(dot1.y, wv[5],  part);
    part = fmaf(dot1.z, wv[6],  part); part = fmaf(dot1.w, wv[7],  part);
    part = fmaf(dot2.x, wv[8],  part); part = fmaf(dot2.y, wv[9],  part);
    part = fmaf(dot2.z, wv[10], part); part = fmaf(dot2.w, wv[11], part);
    part = fmaf(dot3.x, wv[12], part); part = fmaf(dot3.y, wv[13], part);
    part = fmaf(dot3.z, wv[14], part); part = fmaf(dot3.w, wv[15], part);

    // ---- Combine: 8 slots per warp via shfl, then 7 warps via smem ----
    part += __shfl_down_sync(FULL, part, 4);
    part += __shfl_down_sync(FULL, part, 8);
    part += __shfl_down_sync(FULL, part, 16);
    const int lane = tid & 31;
    if (lane < 4) wred[(tid >> 5) * 4 + lane] = part;   // lane == cs == o here
    __syncthreads();

    if (tid < 4) {
        float s = __ldg(bias + tid);
        #pragma unroll
        for (int w = 0; w < 7; w++) s += wred[w * 4 + tid];
        out[b * 4 + tid] = s;
    }
}

extern "C" void kernel_launch(void* const* d_in, const int* in_sizes, int n_in,
                              void* d_out, int out_size)
{
    (void)in_sizes; (void)n_in; (void)out_size;
    const float* p1 = (const float*)d_in[0];   // patch1 [512,128,7,7]
    const float* p2 = (const float*)d_in[1];   // patch2 [512,128,7,7]
    const float* W  = (const float*)d_in[2];   // w_bbox [4,21609]
    const float* bb = (const float*)d_in[3];   // b_bbox [4]
    float* out = (float*)d_out;                // [512,4] fp32

    cudaFuncSetAttribute(corr_head_kernel,
                         cudaFuncAttributeMaxDynamicSharedMemorySize, SMEM_BYTES);

    corr_head_kernel<<<512, 224, SMEM_BYTES>>>(p1, p2, W, bb, out);
}